// round 3
// baseline (speedup 1.0000x reference)
#include <cuda_runtime.h>

// EquivariantLayerNorm, specialized to IRREPS=[(256,0),(128,1),(64,2),(32,3)]
//   dim = 1184, f4/row = 296
//   f4 group ranges: g0 [0,64) g1 [64,160) g2 [160,240) g3 [240,296)
//   element counts: g0=256, g1=384, g2=320, g3=224
//   scalar block = g0 = columns [0,256); scalar_indices is identity there.
// Warp->group map (256 threads, f4 index = t, plus t<40 own f4 t+256):
//   warp 0,1 : g0 (s1, s2_0) + tail g3 via second chunk (s2_3)
//   warp 2-4 : g1        warp 5,6 : g2
//   warp 7   : lanes 0-15 g2, lanes 16-31 g3
// Single barrier per row, double-buffered partials, per-warp final stats.

#define DIM   1184
#define EPSV  1e-5f

__device__ __forceinline__ float wsum32(float v) {
    v += __shfl_xor_sync(0xffffffffu, v, 16);
    v += __shfl_xor_sync(0xffffffffu, v, 8);
    v += __shfl_xor_sync(0xffffffffu, v, 4);
    v += __shfl_xor_sync(0xffffffffu, v, 2);
    v += __shfl_xor_sync(0xffffffffu, v, 1);
    return v;
}
__device__ __forceinline__ float hsum16(float v) {   // sums within each 16-lane half
    v += __shfl_xor_sync(0xffffffffu, v, 8);
    v += __shfl_xor_sync(0xffffffffu, v, 4);
    v += __shfl_xor_sync(0xffffffffu, v, 2);
    v += __shfl_xor_sync(0xffffffffu, v, 1);
    return v;
}

__global__ __launch_bounds__(256) void eln_kernel(const float* __restrict__ x,
                                                  float* __restrict__ out,
                                                  const float* __restrict__ weight,
                                                  const float* __restrict__ bias,
                                                  const int* __restrict__ irrep_idx,
                                                  int nrows) {
    const int t    = threadIdx.x;
    const int warp = t >> 5;
    const int lane = t & 31;
    const bool has1 = (t < 40);          // owns f4 index t+256 (group 3 tail)

    // ---- one-time per-thread init: per-column weight / bias in registers ----
    const int c0 = 4 * t;
    float4 w0, b0 = make_float4(0.f, 0.f, 0.f, 0.f);
    w0.x = weight[irrep_idx[c0 + 0]];
    w0.y = weight[irrep_idx[c0 + 1]];
    w0.z = weight[irrep_idx[c0 + 2]];
    w0.w = weight[irrep_idx[c0 + 3]];
    if (t < 64) {                         // scalar block: bias identity map
        b0.x = bias[c0 + 0];
        b0.y = bias[c0 + 1];
        b0.z = bias[c0 + 2];
        b0.w = bias[c0 + 3];
    }
    float4 w1 = make_float4(0.f, 0.f, 0.f, 0.f);
    if (has1) {
        const int c1 = c0 + 1024;
        w1.x = weight[irrep_idx[c1 + 0]];
        w1.y = weight[irrep_idx[c1 + 1]];
        w1.z = weight[irrep_idx[c1 + 2]];
        w1.w = weight[irrep_idx[c1 + 3]];
    }

    // partial-sum buffers, double buffered (single barrier per row)
    __shared__ float rA[2][2];   // s1   (warp 0,1)
    __shared__ float rB[2][2];   // s2_0 (warp 0,1)
    __shared__ float rC[2][3];   // s2_1 (warp 2,3,4)
    __shared__ float rD[2][3];   // s2_2 (warp 5,6, warp7-lo)
    __shared__ float rE[2][3];   // s2_3 (warp 0,1 tail, warp7-hi)

    int row = blockIdx.x;
    const int    stride    = gridDim.x;
    const size_t stepElems = (size_t)stride * DIM;

    const float4* xr   = (const float4*)(x   + (size_t)row * DIM) + t;
    float4*       orow = (float4*)      (out + (size_t)row * DIM) + t;
    const float4* xr1  = (const float4*)(x   + (size_t)row * DIM) + (t + 256);
    float4*       orow1= (float4*)      (out + (size_t)row * DIM) + (t + 256);
    const size_t  stepF4 = stepElems / 4;

    float4 v0 = make_float4(0.f, 0.f, 0.f, 0.f);
    float4 v1 = make_float4(0.f, 0.f, 0.f, 0.f);
    if (row < nrows) {
        v0 = *xr;
        if (has1) v1 = *xr1;
    }

    int p = 0;
    while (row < nrows) {
        const float q0 = v0.x*v0.x + v0.y*v0.y + v0.z*v0.z + v0.w*v0.w;

        // ---- prefetch next row (overlaps shuffles + barrier) ----
        const int nrow = row + stride;
        float4 nv0 = make_float4(0.f, 0.f, 0.f, 0.f);
        float4 nv1 = make_float4(0.f, 0.f, 0.f, 0.f);
        if (nrow < nrows) {
            nv0 = xr[stepF4];
            if (has1) nv1 = xr1[stepF4];
        }

        // ---- group-aware per-warp reductions ----
        if (warp < 2) {
            float s1 = wsum32(v0.x + v0.y + v0.z + v0.w);
            float s0 = wsum32(q0);
            float q1 = v1.x*v1.x + v1.y*v1.y + v1.z*v1.z + v1.w*v1.w;
            float s3 = wsum32(q1);
            if (lane == 0) { rA[p][warp] = s1; rB[p][warp] = s0; rE[p][warp] = s3; }
        } else if (warp < 5) {
            float s = wsum32(q0);
            if (lane == 0) rC[p][warp - 2] = s;
        } else if (warp < 7) {
            float s = wsum32(q0);
            if (lane == 0) rD[p][warp - 5] = s;
        } else {
            float s = hsum16(q0);                 // lanes 0-15: g2, 16-31: g3
            if (lane == 0)  rD[p][2] = s;
            if (lane == 16) rE[p][2] = s;
        }

        __syncthreads();

        // ---- per-warp final statistics (broadcast LDS, no 2nd barrier) ----
        float rn, sub0 = 0.f, rn3 = 0.f;
        if (warp < 2) {
            const float a0 = rA[p][0] + rA[p][1];
            const float a1 = rB[p][0] + rB[p][1];
            const float smean = a0 * (1.f / 256.f);
            rn   = rsqrtf(a1 * (1.f / 256.f) - smean * smean + EPSV);
            sub0 = smean;
            const float a4 = rE[p][0] + rE[p][1] + rE[p][2];
            rn3  = rsqrtf(a4 * (1.f / 224.f) + EPSV);
        } else if (warp < 5) {
            const float a2 = rC[p][0] + rC[p][1] + rC[p][2];
            rn = rsqrtf(a2 * (1.f / 384.f) + EPSV);
        } else if (warp < 7) {
            const float a3 = rD[p][0] + rD[p][1] + rD[p][2];
            rn = rsqrtf(a3 * (1.f / 320.f) + EPSV);
        } else {
            const float a3 = rD[p][0] + rD[p][1] + rD[p][2];
            const float a4 = rE[p][0] + rE[p][1] + rE[p][2];
            const float r2 = rsqrtf(a3 * (1.f / 320.f) + EPSV);
            const float r3 = rsqrtf(a4 * (1.f / 224.f) + EPSV);
            rn = (lane < 16) ? r2 : r3;
        }

        // ---- write output ----
        {
            float4 o;
            o.x = (v0.x - sub0) * rn * w0.x + b0.x;
            o.y = (v0.y - sub0) * rn * w0.y + b0.y;
            o.z = (v0.z - sub0) * rn * w0.z + b0.z;
            o.w = (v0.w - sub0) * rn * w0.w + b0.w;
            *orow = o;
        }
        if (has1) {
            float4 o;
            o.x = v1.x * rn3 * w1.x;
            o.y = v1.y * rn3 * w1.y;
            o.z = v1.z * rn3 * w1.z;
            o.w = v1.w * rn3 * w1.w;
            *orow1 = o;
        }

        v0 = nv0;
        v1 = nv1;
        row = nrow;
        xr    += stepF4;
        orow  += stepF4;
        xr1   += stepF4;
        orow1 += stepF4;
        p ^= 1;
    }
}

extern "C" void kernel_launch(void* const* d_in, const int* in_sizes, int n_in,
                              void* d_out, int out_size) {
    const float* x         = (const float*)d_in[0];
    const float* weight    = (const float*)d_in[1];
    const float* bias      = (const float*)d_in[2];
    const int*   irrep_idx = (const int*)  d_in[4];

    const int dim = in_sizes[3];           // 1184
    const int n   = in_sizes[0] / dim;     // 65536 rows

    const int grid = 148 * 4;              // persistent, ~111 rows per CTA
    eln_kernel<<<grid, 256>>>(x, (float*)d_out, weight, bias, irrep_idx, n);
}

// round 4
// speedup vs baseline: 3.9222x; 3.9222x over previous
#include <cuda_runtime.h>

// EquivariantLayerNorm, specialized to IRREPS=[(256,0),(128,1),(64,2),(32,3)]
//   dim = 1184, f4-per-row = 296
//   group f4 ranges: g0 [0,64) g1 [64,160) g2 [160,240) g3 [240,296)
//   group element counts: 256, 384, 320, 224
//   scalar block = g0 = columns [0,256); scalar_indices is identity there.
// Persistent kernel, round-2 proven loop body (two barriers, uniform 5-value
// reduce), weight/bias tables built in registers at init (no setup kernel).

#define DIM   1184
#define NF4   296
#define EPSV  1e-5f

__global__ __launch_bounds__(256) void eln_kernel(const float* __restrict__ x,
                                                  float* __restrict__ out,
                                                  const float* __restrict__ weight,
                                                  const float* __restrict__ bias,
                                                  const int* __restrict__ irrep_idx,
                                                  int nrows) {
    const int t = threadIdx.x;
    const bool has1 = (t < NF4 - 256);        // t < 40: also owns f4 index t+256 (group 3)

    // ---- one-time init: per-column weight / bias into registers ----
    const int c0 = 4 * t;
    float4 w0, b0 = make_float4(0.f, 0.f, 0.f, 0.f);
    w0.x = weight[irrep_idx[c0 + 0]];
    w0.y = weight[irrep_idx[c0 + 1]];
    w0.z = weight[irrep_idx[c0 + 2]];
    w0.w = weight[irrep_idx[c0 + 3]];
    if (t < 64) {                             // scalar block: bias identity map
        b0.x = bias[c0 + 0];
        b0.y = bias[c0 + 1];
        b0.z = bias[c0 + 2];
        b0.w = bias[c0 + 3];
    }
    float4 w1 = make_float4(0.f, 0.f, 0.f, 0.f);
    const float4 b1 = make_float4(0.f, 0.f, 0.f, 0.f);
    if (has1) {
        const int c1 = c0 + 1024;
        w1.x = weight[irrep_idx[c1 + 0]];
        w1.y = weight[irrep_idx[c1 + 1]];
        w1.z = weight[irrep_idx[c1 + 2]];
        w1.w = weight[irrep_idx[c1 + 3]];
    }

    __shared__ float red[8][5];
    __shared__ float bc[5];       // {smean, rn0, rn1, rn2, rn3}
    const int warp = t >> 5, lane = t & 31;

    int row = blockIdx.x;
    const int stride = gridDim.x;

    float4 v0 = make_float4(0.f, 0.f, 0.f, 0.f);
    float4 v1 = make_float4(0.f, 0.f, 0.f, 0.f);
    if (row < nrows) {
        const float4* xr = (const float4*)(x + (size_t)row * DIM);
        v0 = xr[t];
        if (has1) v1 = xr[t + 256];
    }

    while (row < nrows) {
        float q0 = v0.x*v0.x + v0.y*v0.y + v0.z*v0.z + v0.w*v0.w;
        float q1 = v1.x*v1.x + v1.y*v1.y + v1.z*v1.z + v1.w*v1.w;

        float s1 = 0.f, s2_0 = 0.f, s2_1 = 0.f, s2_2 = 0.f, s2_3 = 0.f;
        if (t < 64) {                 // group 0 (scalar)
            s2_0 = q0;
            s1   = v0.x + v0.y + v0.z + v0.w;
        } else if (t < 160) {         // group 1
            s2_1 = q0;
        } else if (t < 240) {         // group 2
            s2_2 = q0;
        } else {                      // group 3
            s2_3 = q0;
        }
        s2_3 += q1;                   // extra element is always group 3

        // Prefetch next row while the reduction + barriers run.
        const int nrow = row + stride;
        float4 nv0 = make_float4(0.f, 0.f, 0.f, 0.f);
        float4 nv1 = make_float4(0.f, 0.f, 0.f, 0.f);
        if (nrow < nrows) {
            const float4* nxr = (const float4*)(x + (size_t)nrow * DIM);
            nv0 = nxr[t];
            if (has1) nv1 = nxr[t + 256];
        }

        #pragma unroll
        for (int off = 16; off; off >>= 1) {
            s1   += __shfl_xor_sync(0xffffffffu, s1,   off);
            s2_0 += __shfl_xor_sync(0xffffffffu, s2_0, off);
            s2_1 += __shfl_xor_sync(0xffffffffu, s2_1, off);
            s2_2 += __shfl_xor_sync(0xffffffffu, s2_2, off);
            s2_3 += __shfl_xor_sync(0xffffffffu, s2_3, off);
        }

        if (lane == 0) {
            red[warp][0] = s1;
            red[warp][1] = s2_0;
            red[warp][2] = s2_1;
            red[warp][3] = s2_2;
            red[warp][4] = s2_3;
        }
        __syncthreads();
        if (t == 0) {
            float a0 = 0.f, a1 = 0.f, a2 = 0.f, a3 = 0.f, a4 = 0.f;
            #pragma unroll
            for (int w = 0; w < 8; w++) {
                a0 += red[w][0]; a1 += red[w][1]; a2 += red[w][2];
                a3 += red[w][3]; a4 += red[w][4];
            }
            float smean = a0 * (1.f / 256.f);
            bc[0] = smean;
            bc[1] = rsqrtf(a1 * (1.f / 256.f) - smean * smean + EPSV);
            bc[2] = rsqrtf(a2 * (1.f / 384.f) + EPSV);
            bc[3] = rsqrtf(a3 * (1.f / 320.f) + EPSV);
            bc[4] = rsqrtf(a4 * (1.f / 224.f) + EPSV);
        }
        __syncthreads();

        const float smean = bc[0];
        float rn, sub0 = 0.f;
        if (t < 64)       { rn = bc[1]; sub0 = smean; }
        else if (t < 160) { rn = bc[2]; }
        else if (t < 240) { rn = bc[3]; }
        else              { rn = bc[4]; }
        const float rn3 = bc[4];

        float4* orow = (float4*)(out + (size_t)row * DIM);
        {
            float4 o;
            o.x = (v0.x - sub0) * rn * w0.x + b0.x;
            o.y = (v0.y - sub0) * rn * w0.y + b0.y;
            o.z = (v0.z - sub0) * rn * w0.z + b0.z;
            o.w = (v0.w - sub0) * rn * w0.w + b0.w;
            orow[t] = o;
        }
        if (has1) {
            float4 o;
            o.x = v1.x * rn3 * w1.x + b1.x;
            o.y = v1.y * rn3 * w1.y + b1.y;
            o.z = v1.z * rn3 * w1.z + b1.z;
            o.w = v1.w * rn3 * w1.w + b1.w;
            orow[t + 256] = o;
        }

        v0 = nv0;
        v1 = nv1;
        row = nrow;
    }
}

extern "C" void kernel_launch(void* const* d_in, const int* in_sizes, int n_in,
                              void* d_out, int out_size) {
    const float* x         = (const float*)d_in[0];
    const float* weight    = (const float*)d_in[1];
    const float* bias      = (const float*)d_in[2];
    const int*   irrep_idx = (const int*)  d_in[4];

    const int dim = in_sizes[3];           // 1184
    const int n   = in_sizes[0] / dim;     // 65536 rows

    const int grid = 148 * 4;              // persistent: ~111 rows per CTA
    eln_kernel<<<grid, 256>>>(x, (float*)d_out, weight, bias, irrep_idx, n);
}

// round 5
// speedup vs baseline: 3.9507x; 1.0073x over previous
#include <cuda_runtime.h>

// EquivariantLayerNorm, specialized to IRREPS=[(256,0),(128,1),(64,2),(32,3)]
//   dim = 1184, f4-per-row = 296
//   group f4 ranges: g0 [0,64) g1 [64,160) g2 [160,240) g3 [240,296)
//   group element counts: 256, 384, 320, 224
//   scalar block = g0 = columns [0,256); scalar_indices is identity there.
// Persistent kernel; branch-free 3-slot warp reduction:
//   slotA: q0 masked to warp-primary group    (A[0..1]=g0, A[2..4]=g1, A[5..7]=g2-part)
//   slotB: all group-3 spillover (tail q1 from warps 0-1, warp7-hi q0)
//   slotC: scalar sum (warps 0-1 only)

#define DIM   1184
#define NF4   296
#define EPSV  1e-5f

__global__ __launch_bounds__(256) void eln_kernel(const float* __restrict__ x,
                                                  float* __restrict__ out,
                                                  const float* __restrict__ weight,
                                                  const float* __restrict__ bias,
                                                  const int* __restrict__ irrep_idx,
                                                  int nrows) {
    const int t = threadIdx.x;
    const bool has1   = (t < NF4 - 256);      // t < 40: also owns f4 index t+256 (group 3 tail)
    const bool inPrim = (t < 240);            // false only for warp7 lanes 16-31 (g3)

    // ---- one-time init: per-column weight / bias into registers ----
    const int c0 = 4 * t;
    float4 w0, b0 = make_float4(0.f, 0.f, 0.f, 0.f);
    w0.x = weight[irrep_idx[c0 + 0]];
    w0.y = weight[irrep_idx[c0 + 1]];
    w0.z = weight[irrep_idx[c0 + 2]];
    w0.w = weight[irrep_idx[c0 + 3]];
    if (t < 64) {                             // scalar block: bias identity map
        b0.x = bias[c0 + 0];
        b0.y = bias[c0 + 1];
        b0.z = bias[c0 + 2];
        b0.w = bias[c0 + 3];
    }
    float4 w1 = make_float4(0.f, 0.f, 0.f, 0.f);
    if (has1) {
        const int c1 = c0 + 1024;
        w1.x = weight[irrep_idx[c1 + 0]];
        w1.y = weight[irrep_idx[c1 + 1]];
        w1.z = weight[irrep_idx[c1 + 2]];
        w1.w = weight[irrep_idx[c1 + 3]];
    }

    __shared__ float red[8][3];   // per-warp {slotA, slotB, slotC}
    __shared__ float bc[5];       // {smean, rn0, rn1, rn2, rn3}
    const int warp = t >> 5, lane = t & 31;

    int row = blockIdx.x;
    const int stride = gridDim.x;

    float4 v0 = make_float4(0.f, 0.f, 0.f, 0.f);
    float4 v1 = make_float4(0.f, 0.f, 0.f, 0.f);
    if (row < nrows) {
        const float4* xr = (const float4*)(x + (size_t)row * DIM);
        v0 = xr[t];
        if (has1) v1 = xr[t + 256];
    }

    while (row < nrows) {
        const float q0 = v0.x*v0.x + v0.y*v0.y + v0.z*v0.z + v0.w*v0.w;
        const float q1 = v1.x*v1.x + v1.y*v1.y + v1.z*v1.z + v1.w*v1.w;

        float sA = inPrim   ? q0 : 0.f;
        float sB = inPrim   ? q1 : q0;
        float sC = (t < 64) ? (v0.x + v0.y + v0.z + v0.w) : 0.f;

        // Prefetch next row while the reduction + barriers run.
        const int nrow = row + stride;
        float4 nv0 = make_float4(0.f, 0.f, 0.f, 0.f);
        float4 nv1 = make_float4(0.f, 0.f, 0.f, 0.f);
        if (nrow < nrows) {
            const float4* nxr = (const float4*)(x + (size_t)nrow * DIM);
            nv0 = nxr[t];
            if (has1) nv1 = nxr[t + 256];
        }

        #pragma unroll
        for (int off = 16; off; off >>= 1) {
            sA += __shfl_xor_sync(0xffffffffu, sA, off);
            sB += __shfl_xor_sync(0xffffffffu, sB, off);
            sC += __shfl_xor_sync(0xffffffffu, sC, off);
        }

        if (lane == 0) {
            red[warp][0] = sA;
            red[warp][1] = sB;
            red[warp][2] = sC;
        }
        __syncthreads();
        if (t == 0) {
            const float a0 = red[0][0] + red[1][0];                 // g0 sum-sq
            const float a1 = red[2][0] + red[3][0] + red[4][0];     // g1 sum-sq
            const float a2 = red[5][0] + red[6][0] + red[7][0];     // g2 sum-sq
            float a3 = 0.f, as = 0.f;                               // g3 sum-sq, scalar sum
            #pragma unroll
            for (int w = 0; w < 8; w++) { a3 += red[w][1]; as += red[w][2]; }
            const float smean = as * (1.f / 256.f);
            bc[0] = smean;
            bc[1] = rsqrtf(a0 * (1.f / 256.f) - smean * smean + EPSV);
            bc[2] = rsqrtf(a1 * (1.f / 384.f) + EPSV);
            bc[3] = rsqrtf(a2 * (1.f / 320.f) + EPSV);
            bc[4] = rsqrtf(a3 * (1.f / 224.f) + EPSV);
        }
        __syncthreads();

        const float smean = bc[0];
        float rn, sub0 = 0.f;
        if (t < 64)       { rn = bc[1]; sub0 = smean; }
        else if (t < 160) { rn = bc[2]; }
        else if (t < 240) { rn = bc[3]; }
        else              { rn = bc[4]; }
        const float rn3 = bc[4];

        float4* orow = (float4*)(out + (size_t)row * DIM);
        {
            float4 o;
            o.x = (v0.x - sub0) * rn * w0.x + b0.x;
            o.y = (v0.y - sub0) * rn * w0.y + b0.y;
            o.z = (v0.z - sub0) * rn * w0.z + b0.z;
            o.w = (v0.w - sub0) * rn * w0.w + b0.w;
            orow[t] = o;
        }
        if (has1) {
            float4 o;
            o.x = v1.x * rn3 * w1.x;
            o.y = v1.y * rn3 * w1.y;
            o.z = v1.z * rn3 * w1.z;
            o.w = v1.w * rn3 * w1.w;
            orow[t + 256] = o;
        }

        v0 = nv0;
        v1 = nv1;
        row = nrow;
    }
}

extern "C" void kernel_launch(void* const* d_in, const int* in_sizes, int n_in,
                              void* d_out, int out_size) {
    const float* x         = (const float*)d_in[0];
    const float* weight    = (const float*)d_in[1];
    const float* bias      = (const float*)d_in[2];
    const int*   irrep_idx = (const int*)  d_in[4];

    const int dim = in_sizes[3];           // 1184
    const int n   = in_sizes[0] / dim;     // 65536 rows

    const int grid = 148 * 4;              // persistent: ~111 rows per CTA
    eln_kernel<<<grid, 256>>>(x, (float*)d_out, weight, bias, irrep_idx, n);
}